// round 7
// baseline (speedup 1.0000x reference)
#include <cuda_runtime.h>
#include <cuda_bf16.h>

// LIF recurrence over T=4 steps.
// x: [T=4, B=64, C=128, H=32, W=32] fp32; mem0: [1, C, H, W] fp32 (B-broadcast)
// out: [T, B, C, H, W] fp32 in {0,1}
// Per element: mem = tau*mem + x[t]; s = (mem > v_th); mem = s ? 0 : mem.
//
// HBM-bound at the mixed R/W stream floor (~7.4 TB/s effective).
// 1 float4/thread, 256-thread blocks (8192 CTAs: fine-grain tail balance),
// 4 front-batched evict-first LDG.128, evict-first STG.128, 32 regs.

#define TAU 0.25f
#define V_TH 1.0f

__device__ __forceinline__ void lif_step(float4& mem, const float4& xt, float4& s) {
    mem.x = TAU * mem.x + xt.x; s.x = (mem.x > V_TH) ? 1.0f : 0.0f; mem.x = (mem.x > V_TH) ? 0.0f : mem.x;
    mem.y = TAU * mem.y + xt.y; s.y = (mem.y > V_TH) ? 1.0f : 0.0f; mem.y = (mem.y > V_TH) ? 0.0f : mem.y;
    mem.z = TAU * mem.z + xt.z; s.z = (mem.z > V_TH) ? 1.0f : 0.0f; mem.z = (mem.z > V_TH) ? 0.0f : mem.z;
    mem.w = TAU * mem.w + xt.w; s.w = (mem.w > V_TH) ? 1.0f : 0.0f; mem.w = (mem.w > V_TH) ? 0.0f : mem.w;
}

__global__ __launch_bounds__(256) void lif_kernel(
    const float4* __restrict__ x,
    const float4* __restrict__ mem0,
    float4* __restrict__ out,
    int n4)          // float4 units per timestep: B*C*H*W/4 = 2,097,152
{
    int i = blockIdx.x * blockDim.x + threadIdx.x;
    if (i >= n4) return;

    // CHW/4 = 128*32*32/4 = 32768 = 2^15 -> mask for B-broadcast of mem0
    const int CHW4_MASK = 32767;
    float4 mem = __ldg(&mem0[i & CHW4_MASK]);

    // Front-batch the 4 streaming loads (evict-first), 64 B in flight/thread.
    float4 x0 = __ldcs(&x[0 * (size_t)n4 + i]);
    float4 x1 = __ldcs(&x[1 * (size_t)n4 + i]);
    float4 x2 = __ldcs(&x[2 * (size_t)n4 + i]);
    float4 x3 = __ldcs(&x[3 * (size_t)n4 + i]);

    float4 s;
    lif_step(mem, x0, s); __stcs(&out[0 * (size_t)n4 + i], s);
    lif_step(mem, x1, s); __stcs(&out[1 * (size_t)n4 + i], s);
    lif_step(mem, x2, s); __stcs(&out[2 * (size_t)n4 + i], s);
    lif_step(mem, x3, s); __stcs(&out[3 * (size_t)n4 + i], s);
}

extern "C" void kernel_launch(void* const* d_in, const int* in_sizes, int n_in,
                              void* d_out, int out_size) {
    const float4* x    = (const float4*)d_in[0];   // [4, 64, 128, 32, 32]
    const float4* mem0 = (const float4*)d_in[1];   // [1, 128, 32, 32]
    float4* out = (float4*)d_out;

    int n_per_t = in_sizes[0] / 4;       // 8,388,608 elems per timestep
    int n4 = n_per_t / 4;                // 2,097,152 float4 units

    int threads = 256;
    int blocks = (n4 + threads - 1) / threads;   // 8192
    lif_kernel<<<blocks, threads>>>(x, mem0, out, n4);
}